// round 3
// baseline (speedup 1.0000x reference)
#include <cuda_runtime.h>
#include <float.h>

// Problem constants (fixed by setup_inputs):
//   x: (64,32,32,64) fp32  -> 65536 rows of D=64
//   embedding: (64,4096)   -> D=64, K=4096 (stored D-major: E[d*K+k])
#define Dm     64
#define Kcb    4096
#define NROWS  65536
#define TK     64                 // codewords per smem tile
#define TPB    64                 // threads per block (1 row per thread)
#define NBLK   (NROWS / TPB)      // 1024 main blocks -> ~99% SM balance

typedef unsigned long long u64;

// Scratch (no cudaMalloc allowed)
__device__ float  g_eT[Kcb * Dm];     // codebook transposed, K-major: g_eT[k*64+d]
__device__ float  g_enorm[Kcb];       // ||e_k||^2
__device__ double g_p1[NBLK];         // per-block sum(diff)
__device__ double g_p2[NBLK];         // per-block sum(diff^2)

// Packed fp32x2 ops (sm_100+; each lane is an independent rn op, numerically
// identical to two scalar fmaf/fadd).
#define FMA2(d, a, b, c) \
    asm("fma.rn.f32x2 %0, %1, %2, %3;" : "=l"(d) : "l"(a), "l"(b), "l"(c))
#define ADD2(d, a, b) \
    asm("add.rn.f32x2 %0, %1, %2;" : "=l"(d) : "l"(a), "l"(b))

__device__ __forceinline__ float f2lo(u64 v) { return __uint_as_float((unsigned)v); }
__device__ __forceinline__ float f2hi(u64 v) { return __uint_as_float((unsigned)(v >> 32)); }

// ---------------------------------------------------------------------------
// Kernel 1: codebook norms + transpose. 4096 threads, one codeword each.
// Reads E[d*K+k] coalesced across k.
// ---------------------------------------------------------------------------
__global__ void vq_prep(const float* __restrict__ E) {
    int k = blockIdx.x * blockDim.x + threadIdx.x;
    if (k >= Kcb) return;
    float nrm = 0.0f;
    #pragma unroll
    for (int d = 0; d < Dm; ++d) {
        float v = E[d * Kcb + k];
        g_eT[k * Dm + d] = v;
        nrm = fmaf(v, v, nrm);
    }
    g_enorm[k] = nrm;
}

// ---------------------------------------------------------------------------
// Kernel 2: fused distance GEMM (f32x2-packed) + argmin + gather + estimator
// + loss partials. One row per thread; row resident as 32 u64 dim-pairs.
// Codebook streamed through smem in 64x64 tiles (16 KB), stored as 16-byte
// ulonglong2 so the inner d-loop is 16 broadcast LDS.128 per codeword
// (guaranteed vector width -> LDS pipe stays below the fma pipe).
// Score mimics the reference rounding: d = rn( rn(||f||^2+||e||^2) - 2*dot ),
// the final step in one fmaf (2*dot is exact) -> same last rounding as jax.
// ---------------------------------------------------------------------------
__global__ __launch_bounds__(TPB)
void vq_main(const float* __restrict__ x, float* __restrict__ out) {
    __shared__ __align__(16) ulonglong2 sE[TK * 16];  // 16 KB: 16 x u64x2 per codeword
    __shared__ float  sN[TK];
    __shared__ double red1[TPB];
    __shared__ double red2[TPB];

    const int tid = threadIdx.x;
    const int row = blockIdx.x * TPB + tid;

    // Row into registers as 32 dim-pairs (little-endian: low word = even dim).
    u64 f[32];
    const u64* xr = (const u64*)(x + (size_t)row * Dm);
    #pragma unroll
    for (int i = 0; i < 32; ++i) f[i] = xr[i];

    // ||f||^2
    u64 n0 = 0ull, n1 = 0ull, n2 = 0ull, n3 = 0ull;
    #pragma unroll
    for (int i = 0; i < 32; i += 4) {
        FMA2(n0, f[i + 0], f[i + 0], n0);
        FMA2(n1, f[i + 1], f[i + 1], n1);
        FMA2(n2, f[i + 2], f[i + 2], n2);
        FMA2(n3, f[i + 3], f[i + 3], n3);
    }
    u64 ns01, ns23, ns;
    ADD2(ns01, n0, n1); ADD2(ns23, n2, n3); ADD2(ns, ns01, ns23);
    const float nf = __fadd_rn(f2lo(ns), f2hi(ns));

    float best = FLT_MAX;
    int   bidx = 0;

    for (int k0 = 0; k0 < Kcb; k0 += TK) {
        __syncthreads();
        // Cooperative tile load (1024 x 16B, 16 per thread, coalesced).
        const ulonglong2* src =
            (const ulonglong2*)(g_eT + (size_t)k0 * Dm);
        #pragma unroll
        for (int i = 0; i < 16; ++i)
            sE[tid + i * TPB] = src[tid + i * TPB];
        sN[tid] = g_enorm[k0 + tid];
        __syncthreads();

        for (int kk = 0; kk < TK; ++kk) {
            const ulonglong2* e = &sE[kk * 16];
            u64 a0 = 0ull, a1 = 0ull, a2 = 0ull, a3 = 0ull;
            #pragma unroll
            for (int i = 0; i < 16; i += 2) {
                ulonglong2 e0 = e[i];          // broadcast LDS.128 (dims 4i..4i+3)
                ulonglong2 e1 = e[i + 1];      // broadcast LDS.128 (dims 4i+4..4i+7)
                FMA2(a0, e0.x, f[2 * i + 0], a0);
                FMA2(a1, e0.y, f[2 * i + 1], a1);
                FMA2(a2, e1.x, f[2 * i + 2], a2);
                FMA2(a3, e1.y, f[2 * i + 3], a3);
            }
            u64 s01, s23, s;
            ADD2(s01, a0, a1); ADD2(s23, a2, a3); ADD2(s, s01, s23);
            float dot = __fadd_rn(f2lo(s), f2hi(s));
            float t   = __fadd_rn(nf, sN[kk]);            // rn(||f||^2 + ||e||^2)
            float sc  = __fmaf_rn(-2.0f, dot, t);         // rn(t - 2*dot): matches ref
            if (sc < best) { best = sc; bidx = k0 + kk; } // strict '<' = first-index wins
        }
    }

    // Epilogue: gather chosen codeword, estimator exactly as the reference
    // rounds it (x + (q - x)), loss partials.
    const float4* q4 = (const float4*)(g_eT + (size_t)bidx * Dm);
    float4* o4 = (float4*)(out + (size_t)row * Dm);
    float s1 = 0.f, s2 = 0.f;
    #pragma unroll
    for (int i = 0; i < 16; ++i) {
        float4 q = q4[i];
        float fx = f2lo(f[2 * i]),     fy = f2hi(f[2 * i]);
        float fz = f2lo(f[2 * i + 1]), fw = f2hi(f[2 * i + 1]);
        float dx = __fsub_rn(q.x, fx);
        float dy = __fsub_rn(q.y, fy);
        float dz = __fsub_rn(q.z, fz);
        float dw = __fsub_rn(q.w, fw);
        float4 est;
        est.x = __fadd_rn(fx, dx);
        est.y = __fadd_rn(fy, dy);
        est.z = __fadd_rn(fz, dz);
        est.w = __fadd_rn(fw, dw);
        o4[i] = est;
        s1 += ((dx + dy) + (dz + dw));
        s2 = fmaf(dx, dx, s2);
        s2 = fmaf(dy, dy, s2);
        s2 = fmaf(dz, dz, s2);
        s2 = fmaf(dw, dw, s2);
    }

    // Deterministic block reduction (fixed tree, double precision).
    red1[tid] = (double)s1;
    red2[tid] = (double)s2;
    __syncthreads();
    #pragma unroll
    for (int off = TPB / 2; off > 0; off >>= 1) {
        if (tid < off) {
            red1[tid] += red1[tid + off];
            red2[tid] += red2[tid + off];
        }
        __syncthreads();
    }
    if (tid == 0) {
        g_p1[blockIdx.x] = red1[0];
        g_p2[blockIdx.x] = red2[0];
    }
}

// ---------------------------------------------------------------------------
// Kernel 3: final loss (single block, fixed order -> deterministic).
// loss = 0.25 * mean(diff)^2 + mean(diff^2)
// ---------------------------------------------------------------------------
__global__ void vq_finalize(float* __restrict__ loss_out) {
    __shared__ double r1[128];
    __shared__ double r2[128];
    const int t = threadIdx.x;
    double s1 = 0.0, s2 = 0.0;
    for (int i = t; i < NBLK; i += 128) { s1 += g_p1[i]; s2 += g_p2[i]; }
    r1[t] = s1; r2[t] = s2;
    __syncthreads();
    #pragma unroll
    for (int off = 64; off > 0; off >>= 1) {
        if (t < off) { r1[t] += r1[t + off]; r2[t] += r2[t + off]; }
        __syncthreads();
    }
    if (t == 0) {
        const double M = (double)NROWS * (double)Dm;   // 4194304
        double m1 = r1[0] / M;
        double loss = 0.25 * m1 * m1 + r2[0] / M;
        *loss_out = (float)loss;
    }
}

// ---------------------------------------------------------------------------
extern "C" void kernel_launch(void* const* d_in, const int* in_sizes, int n_in,
                              void* d_out, int out_size) {
    (void)in_sizes; (void)n_in;
    const float* x = (const float*)d_in[0];   // 4194304 floats
    const float* E = (const float*)d_in[1];   // 262144 floats (64 x 4096)
    float* out = (float*)d_out;

    vq_prep<<<(Kcb + 127) / 128, 128>>>(E);
    vq_main<<<NBLK, TPB>>>(x, out);
    if (out_size > NROWS * Dm) {
        vq_finalize<<<1, 128>>>(out + (size_t)NROWS * Dm);
    }
}

// round 5
// speedup vs baseline: 1.8799x; 1.8799x over previous
#include <cuda_runtime.h>
#include <cuda_bf16.h>
#include <float.h>
#include <stdint.h>

// Problem: x (65536 rows x 64 fp32), embedding (64 x 4096 fp32, D-major)
#define Dm      64
#define Kcb     4096
#define NROWS   65536
#define MCTA    128                  // rows per CTA
#define NCTA    (NROWS / MCTA)       // 512
#define NTILE   64                   // codewords per tile
#define NTILES  (Kcb / NTILE)        // 64
#define TAU     1e-3f

typedef unsigned long long u64;

// ------------------------- device scratch (no mallocs) ----------------------
__device__ float          g_eT[Kcb * Dm];      // fp32 codebook K-major (gather + fallback)
__device__ float          g_enorm[Kcb];        // ||e||^2
__device__ __nv_bfloat16  g_eb0[Kcb * Dm];     // bf16 hi split, K-major
__device__ __nv_bfloat16  g_eb1[Kcb * Dm];     // bf16 residual split
__device__ __nv_bfloat16  g_xb0[NROWS * Dm];   // x hi split (row-major)
__device__ __nv_bfloat16  g_xb1[NROWS * Dm];   // x residual split
__device__ float          g_rs1[NROWS];        // per-row sum(diff)
__device__ float          g_rs2[NROWS];        // per-row sum(diff^2)
__device__ int            g_nflag;
__device__ int            g_flaglist[NROWS];

// ------------------------- PTX helpers (base ISA only, no 'a' features) -----
__device__ __forceinline__ uint32_t smem_u32(const void* p) {
    uint32_t a;
    asm("{ .reg .u64 t; cvta.to.shared.u64 t, %1; cvt.u32.u64 %0, t; }" : "=r"(a) : "l"(p));
    return a;
}
#define CP_ASYNC16(dst, src) \
    asm volatile("cp.async.ca.shared.global [%0], [%1], 16;" :: "r"(dst), "l"(src) : "memory")
#define CP_COMMIT()  asm volatile("cp.async.commit_group;" ::: "memory")
#define CP_WAIT1()   asm volatile("cp.async.wait_group 1;" ::: "memory")

__device__ __forceinline__ void ldsm_x4(uint32_t* r, uint32_t addr) {
    asm volatile("ldmatrix.sync.aligned.m8n8.x4.shared.b16 {%0,%1,%2,%3}, [%4];"
        : "=r"(r[0]), "=r"(r[1]), "=r"(r[2]), "=r"(r[3]) : "r"(addr));
}
__device__ __forceinline__ void mma16816(float* d, const uint32_t* a, uint32_t b0, uint32_t b1) {
    asm volatile("mma.sync.aligned.m16n8k16.row.col.f32.bf16.bf16.f32 "
        "{%0,%1,%2,%3}, {%4,%5,%6,%7}, {%8,%9}, {%0,%1,%2,%3};"
        : "+f"(d[0]), "+f"(d[1]), "+f"(d[2]), "+f"(d[3])
        : "r"(a[0]), "r"(a[1]), "r"(a[2]), "r"(a[3]), "r"(b0), "r"(b1));
}
#define SW128(o) ((o) ^ (((o) >> 3) & 0x70))

// Packed fp32x2 (exact fallback scoring — bit-identical to the proven v3 path)
#define FMA2(d, a, b, c) asm("fma.rn.f32x2 %0, %1, %2, %3;" : "=l"(d) : "l"(a), "l"(b), "l"(c))
#define ADD2(d, a, b)    asm("add.rn.f32x2 %0, %1, %2;" : "=l"(d) : "l"(a), "l"(b))
__device__ __forceinline__ float f2lo(u64 v) { return __uint_as_float((unsigned)v); }
__device__ __forceinline__ float f2hi(u64 v) { return __uint_as_float((unsigned)(v >> 32)); }

// ---------------------------------------------------------------------------
// Prep 1: codebook -> fp32 transpose + norms + bf16 splits. One thread per k.
// ---------------------------------------------------------------------------
__global__ void vq_prep_e(const float* __restrict__ E) {
    int k = blockIdx.x * blockDim.x + threadIdx.x;
    if (k == 0) g_nflag = 0;
    if (k >= Kcb) return;
    float nrm = 0.0f;
    #pragma unroll
    for (int d = 0; d < Dm; ++d) {
        float v = E[d * Kcb + k];
        g_eT[k * Dm + d] = v;
        __nv_bfloat16 b0 = __float2bfloat16_rn(v);
        float r = v - __bfloat162float(b0);
        g_eb0[k * Dm + d] = b0;
        g_eb1[k * Dm + d] = __float2bfloat16_rn(r);
        nrm = fmaf(v, v, nrm);
    }
    g_enorm[k] = nrm;
}

// ---------------------------------------------------------------------------
// Prep 2: x -> bf16 splits. One float4 per thread.
// ---------------------------------------------------------------------------
__global__ void vq_prep_x(const float* __restrict__ x) {
    int i = blockIdx.x * blockDim.x + threadIdx.x;
    if (i >= (NROWS * Dm) / 4) return;
    float4 v = ((const float4*)x)[i];
    float vv[4] = {v.x, v.y, v.z, v.w};
    unsigned short hp[4], lp[4];
    #pragma unroll
    for (int j = 0; j < 4; ++j) {
        __nv_bfloat16 h = __float2bfloat16_rn(vv[j]);
        __nv_bfloat16 l = __float2bfloat16_rn(vv[j] - __bfloat162float(h));
        hp[j] = *(unsigned short*)&h;
        lp[j] = *(unsigned short*)&l;
    }
    ((u64*)g_xb0)[i] = (u64)hp[0] | ((u64)hp[1] << 16) | ((u64)hp[2] << 32) | ((u64)hp[3] << 48);
    ((u64*)g_xb1)[i] = (u64)lp[0] | ((u64)lp[1] << 16) | ((u64)lp[2] << 32) | ((u64)lp[3] << 48);
}

// ---------------------------------------------------------------------------
// Main: split-bf16 mma.sync GEMM + fused approx-argmin with certainty margin.
// 256 threads = 8 warps; warp w owns rows [row0+16w, row0+16w+16).
// ---------------------------------------------------------------------------
__global__ __launch_bounds__(256, 2)
void vq_mma(const float* __restrict__ x, float* __restrict__ out) {
    __shared__ __align__(128) char  sB[2][2][NTILE * 128];  // [buf][split] 8KB tiles
    __shared__ __align__(16)  float sN[2][NTILE];

    const int tid  = threadIdx.x;
    const int lane = tid & 31;
    const int w    = tid >> 5;
    const int row0 = blockIdx.x * MCTA;
    const uint32_t sb = smem_u32(sB);
    const uint32_t sbn = smem_u32(sN);

    // --- A fragments (register resident): rows row0+16w+(lane/4), +8 --------
    const int rA = row0 + w * 16 + (lane >> 2);
    const int cb = 2 * (lane & 3);
    uint32_t a0[4][4], a1[4][4];
    #pragma unroll
    for (int kc = 0; kc < 4; ++kc) {
        const int c = kc * 16 + cb;
        a0[kc][0] = *(const uint32_t*)(g_xb0 + (size_t)rA * Dm + c);
        a0[kc][1] = *(const uint32_t*)(g_xb0 + (size_t)(rA + 8) * Dm + c);
        a0[kc][2] = *(const uint32_t*)(g_xb0 + (size_t)rA * Dm + c + 8);
        a0[kc][3] = *(const uint32_t*)(g_xb0 + (size_t)(rA + 8) * Dm + c + 8);
        a1[kc][0] = *(const uint32_t*)(g_xb1 + (size_t)rA * Dm + c);
        a1[kc][1] = *(const uint32_t*)(g_xb1 + (size_t)(rA + 8) * Dm + c);
        a1[kc][2] = *(const uint32_t*)(g_xb1 + (size_t)rA * Dm + c + 8);
        a1[kc][3] = *(const uint32_t*)(g_xb1 + (size_t)(rA + 8) * Dm + c + 8);
    }

    // ldmatrix per-lane constants: matrix m = lane/8, row-in-matrix = lane%8
    const int lm  = lane >> 3;
    const int lrow = ((lm >> 1) << 3) + (lane & 7);   // +8 rows for matrices 2,3
    const int lcb  = (lm & 1) << 4;                   // +16B for matrices 1,3

    // --- prefetch tile 0 ----------------------------------------------------
    {
        const char* s0 = (const char*)(g_eb0);
        const char* s1 = (const char*)(g_eb1);
        #pragma unroll
        for (int r = 0; r < 2; ++r) {
            int c = tid + r * 256;                    // chunk 0..511
            uint32_t d0 = sb + SW128(c * 16);
            uint32_t d1 = sb + 8192 + SW128(c * 16);
            CP_ASYNC16(d0, s0 + c * 16);
            CP_ASYNC16(d1, s1 + c * 16);
        }
        if (tid < 16) CP_ASYNC16(sbn + tid * 16, (const char*)g_enorm + tid * 16);
    }
    CP_COMMIT();

    // per-row argmin state: half A = row rA, half B = row rA+8
    float m1A = FLT_MAX, m2A = FLT_MAX, m1B = FLT_MAX, m2B = FLT_MAX;
    int   i1A = 0, i1B = 0;

    for (int nt = 0; nt < NTILES; ++nt) {
        const int buf = nt & 1;
        // prefetch tile nt+1 into other buffer
        if (nt + 1 < NTILES) {
            const char* s0 = (const char*)(g_eb0 + (size_t)(nt + 1) * NTILE * Dm);
            const char* s1 = (const char*)(g_eb1 + (size_t)(nt + 1) * NTILE * Dm);
            uint32_t base = sb + (buf ^ 1) * 16384;
            #pragma unroll
            for (int r = 0; r < 2; ++r) {
                int c = tid + r * 256;
                CP_ASYNC16(base + SW128(c * 16), s0 + c * 16);
                CP_ASYNC16(base + 8192 + SW128(c * 16), s1 + c * 16);
            }
            if (tid < 16)
                CP_ASYNC16(sbn + (buf ^ 1) * 256 + tid * 16,
                           (const char*)(g_enorm + (nt + 1) * NTILE) + tid * 16);
        }
        CP_COMMIT();
        CP_WAIT1();
        __syncthreads();

        float acc[8][4];
        #pragma unroll
        for (int j = 0; j < 8; ++j) {
            acc[j][0] = 0.f; acc[j][1] = 0.f; acc[j][2] = 0.f; acc[j][3] = 0.f;
        }
        const uint32_t bbase = sb + buf * 16384;
        #pragma unroll
        for (int kc = 0; kc < 4; ++kc) {
            #pragma unroll
            for (int p = 0; p < 4; ++p) {             // ntiles 2p, 2p+1
                uint32_t off = SW128((p * 16 + lrow) * 128 + kc * 32 + lcb);
                uint32_t bb0[4], bb1[4];
                ldsm_x4(bb0, bbase + off);            // split 0
                ldsm_x4(bb1, bbase + 8192 + off);     // split 1
                mma16816(acc[2 * p],     a0[kc], bb0[0], bb0[1]);
                mma16816(acc[2 * p],     a1[kc], bb0[0], bb0[1]);
                mma16816(acc[2 * p],     a0[kc], bb1[0], bb1[1]);
                mma16816(acc[2 * p + 1], a0[kc], bb0[2], bb0[3]);
                mma16816(acc[2 * p + 1], a1[kc], bb0[2], bb0[3]);
                mma16816(acc[2 * p + 1], a0[kc], bb1[2], bb1[3]);
            }
        }
        // scores + argmin update (k ascending within lane)
        const float* np = sN[buf];
        #pragma unroll
        for (int j = 0; j < 8; ++j) {
            const int k0 = nt * NTILE + j * 8 + cb;
            float n0 = np[j * 8 + cb], n1 = np[j * 8 + cb + 1];
            float sA0 = __fmaf_rn(-2.f, acc[j][0], n0);
            float sA1 = __fmaf_rn(-2.f, acc[j][1], n1);
            float sB0 = __fmaf_rn(-2.f, acc[j][2], n0);
            float sB1 = __fmaf_rn(-2.f, acc[j][3], n1);
            if (sA0 < m1A) { m2A = m1A; m1A = sA0; i1A = k0; } else if (sA0 < m2A) m2A = sA0;
            if (sA1 < m1A) { m2A = m1A; m1A = sA1; i1A = k0 + 1; } else if (sA1 < m2A) m2A = sA1;
            if (sB0 < m1B) { m2B = m1B; m1B = sB0; i1B = k0; } else if (sB0 < m2B) m2B = sB0;
            if (sB1 < m1B) { m2B = m1B; m1B = sB1; i1B = k0 + 1; } else if (sB1 < m2B) m2B = sB1;
        }
        __syncthreads();   // all warps done reading buf before it is refilled
    }

    // cross-lane merge within groups of 4 (lanes 4g..4g+3 share a row)
    #pragma unroll
    for (int d = 1; d <= 2; d <<= 1) {
        float om1 = __shfl_xor_sync(~0u, m1A, d);
        float om2 = __shfl_xor_sync(~0u, m2A, d);
        int   oi1 = __shfl_xor_sync(~0u, i1A, d);
        if (om1 < m1A || (om1 == m1A && oi1 < i1A)) {
            m2A = fminf(m1A, om2); m1A = om1; i1A = oi1;
        } else {
            m2A = fminf(m2A, om1);
        }
        om1 = __shfl_xor_sync(~0u, m1B, d);
        om2 = __shfl_xor_sync(~0u, m2B, d);
        oi1 = __shfl_xor_sync(~0u, i1B, d);
        if (om1 < m1B || (om1 == m1B && oi1 < i1B)) {
            m2B = fminf(m1B, om2); m1B = om1; i1B = oi1;
        } else {
            m2B = fminf(m2B, om1);
        }
    }

    // per-row decision + exact epilogue (4 lanes cooperate per row)
    const int q = lane & 3;
    #pragma unroll
    for (int h = 0; h < 2; ++h) {
        const int row = (h == 0) ? rA : rA + 8;
        const float m1 = (h == 0) ? m1A : m1B;
        const float m2 = (h == 0) ? m2A : m2B;
        const int   i1 = (h == 0) ? i1A : i1B;
        if (m2 - m1 < TAU) {
            if (q == 0) {
                int slot = atomicAdd(&g_nflag, 1);
                g_flaglist[slot] = row;
            }
        } else {
            const float4* q4 = (const float4*)(g_eT + (size_t)i1 * Dm) + q * 4;
            const float4* xr = (const float4*)(x + (size_t)row * Dm) + q * 4;
            float4* o4 = (float4*)(out + (size_t)row * Dm) + q * 4;
            float s1 = 0.f, s2 = 0.f;
            #pragma unroll
            for (int i = 0; i < 4; ++i) {
                float4 qq = q4[i], fv = xr[i];
                float dx = __fsub_rn(qq.x, fv.x);
                float dy = __fsub_rn(qq.y, fv.y);
                float dz = __fsub_rn(qq.z, fv.z);
                float dw = __fsub_rn(qq.w, fv.w);
                float4 est;
                est.x = __fadd_rn(fv.x, dx);
                est.y = __fadd_rn(fv.y, dy);
                est.z = __fadd_rn(fv.z, dz);
                est.w = __fadd_rn(fv.w, dw);
                o4[i] = est;
                s1 += ((dx + dy) + (dz + dw));
                s2 = fmaf(dx, dx, s2); s2 = fmaf(dy, dy, s2);
                s2 = fmaf(dz, dz, s2); s2 = fmaf(dw, dw, s2);
            }
            s1 += __shfl_xor_sync(~0u, s1, 1);
            s2 += __shfl_xor_sync(~0u, s2, 1);
            s1 += __shfl_xor_sync(~0u, s1, 2);
            s2 += __shfl_xor_sync(~0u, s2, 2);
            if (q == 0) { g_rs1[row] = s1; g_rs2[row] = s2; }
        }
    }
}

// ---------------------------------------------------------------------------
// Fallback: exact fp32 rescan of flagged rows (bit-identical scoring to the
// proven v3 kernel). One warp per flagged row.
// ---------------------------------------------------------------------------
__global__ __launch_bounds__(128)
void vq_fallback(const float* __restrict__ x, float* __restrict__ out) {
    const int lane = threadIdx.x & 31;
    const int gw = (blockIdx.x * blockDim.x + threadIdx.x) >> 5;
    const int nwarps = (gridDim.x * blockDim.x) >> 5;
    const int nf = g_nflag;

    for (int it = gw; it < nf; it += nwarps) {
        const int row = g_flaglist[it];
        u64 f[32];
        const u64* xr = (const u64*)(x + (size_t)row * Dm);
        #pragma unroll
        for (int i = 0; i < 32; ++i) f[i] = xr[i];

        u64 n0 = 0ull, n1 = 0ull, n2 = 0ull, n3 = 0ull;
        #pragma unroll
        for (int i = 0; i < 32; i += 4) {
            FMA2(n0, f[i + 0], f[i + 0], n0);
            FMA2(n1, f[i + 1], f[i + 1], n1);
            FMA2(n2, f[i + 2], f[i + 2], n2);
            FMA2(n3, f[i + 3], f[i + 3], n3);
        }
        u64 ns01, ns23, ns;
        ADD2(ns01, n0, n1); ADD2(ns23, n2, n3); ADD2(ns, ns01, ns23);
        const float nfv = __fadd_rn(f2lo(ns), f2hi(ns));

        float best = FLT_MAX;
        int bidx = 0x7fffffff;
        for (int j = 0; j < Kcb / 32; ++j) {
            const int k = j * 32 + lane;
            const ulonglong2* e = (const ulonglong2*)(g_eT + (size_t)k * Dm);
            u64 a0 = 0ull, a1 = 0ull, a2 = 0ull, a3 = 0ull;
            #pragma unroll
            for (int i = 0; i < 16; i += 2) {
                ulonglong2 e0 = e[i], e1 = e[i + 1];
                FMA2(a0, e0.x, f[2 * i + 0], a0);
                FMA2(a1, e0.y, f[2 * i + 1], a1);
                FMA2(a2, e1.x, f[2 * i + 2], a2);
                FMA2(a3, e1.y, f[2 * i + 3], a3);
            }
            u64 s01, s23, s;
            ADD2(s01, a0, a1); ADD2(s23, a2, a3); ADD2(s, s01, s23);
            float dot = __fadd_rn(f2lo(s), f2hi(s));
            float tt = __fadd_rn(nfv, g_enorm[k]);
            float sc = __fmaf_rn(-2.0f, dot, tt);
            if (sc < best) { best = sc; bidx = k; }
        }
        #pragma unroll
        for (int off = 16; off > 0; off >>= 1) {   // argmin, smallest-k tie-break
            float ob = __shfl_xor_sync(0xffffffffu, best, off);
            int oi = __shfl_xor_sync(0xffffffffu, bidx, off);
            if (ob < best || (ob == best && oi < bidx)) { best = ob; bidx = oi; }
        }
        const float fx = f2lo(f[lane]), fy = f2hi(f[lane]);
        const float* qp = g_eT + (size_t)bidx * Dm;
        float qx = qp[2 * lane], qy = qp[2 * lane + 1];
        float dx = __fsub_rn(qx, fx), dy = __fsub_rn(qy, fy);
        out[(size_t)row * Dm + 2 * lane] = __fadd_rn(fx, dx);
        out[(size_t)row * Dm + 2 * lane + 1] = __fadd_rn(fy, dy);
        float s1 = dx + dy;
        float s2 = fmaf(dx, dx, 0.f); s2 = fmaf(dy, dy, s2);
        #pragma unroll
        for (int off = 16; off > 0; off >>= 1) {
            s1 += __shfl_xor_sync(0xffffffffu, s1, off);
            s2 += __shfl_xor_sync(0xffffffffu, s2, off);
        }
        if (lane == 0) { g_rs1[row] = s1; g_rs2[row] = s2; }
    }
}

// ---------------------------------------------------------------------------
// Finalize loss: deterministic fixed-order fp64 sum over per-row partials.
// loss = 0.25 * mean(diff)^2 + mean(diff^2)
// ---------------------------------------------------------------------------
__global__ void vq_finalize(float* __restrict__ loss_out) {
    __shared__ double r1[1024], r2[1024];
    const int t = threadIdx.x;
    double s1 = 0.0, s2 = 0.0;
    for (int i = t; i < NROWS; i += 1024) { s1 += (double)g_rs1[i]; s2 += (double)g_rs2[i]; }
    r1[t] = s1; r2[t] = s2;
    __syncthreads();
    #pragma unroll
    for (int off = 512; off > 0; off >>= 1) {
        if (t < off) { r1[t] += r1[t + off]; r2[t] += r2[t + off]; }
        __syncthreads();
    }
    if (t == 0) {
        const double M = (double)NROWS * (double)Dm;
        double m1 = r1[0] / M;
        *loss_out = (float)(0.25 * m1 * m1 + r2[0] / M);
    }
}

// ---------------------------------------------------------------------------
extern "C" void kernel_launch(void* const* d_in, const int* in_sizes, int n_in,
                              void* d_out, int out_size) {
    (void)in_sizes; (void)n_in;
    const float* x = (const float*)d_in[0];
    const float* E = (const float*)d_in[1];
    float* out = (float*)d_out;

    vq_prep_e<<<(Kcb + 127) / 128, 128>>>(E);
    vq_prep_x<<<(NROWS * Dm / 4 + 255) / 256, 256>>>(x);
    vq_mma<<<NCTA, 256>>>(x, out);
    vq_fallback<<<256, 128>>>(x, out);
    if (out_size > NROWS * Dm) {
        vq_finalize<<<1, 1024>>>(out + (size_t)NROWS * Dm);
    }
}